// round 16
// baseline (speedup 1.0000x reference)
#include <cuda_runtime.h>
#include <cuda_bf16.h>
#include <math.h>

// ---------------- static config ----------------
#define BB    8
#define SS    256
#define CC    128
#define HWD   256
#define TOK_STRIDE 32768            // CC*HWD
#define TOTAL (BB*SS*CC*HWD)

// ---------------- scratch ----------------
__device__ float g_q[TOTAL];        // Q(bf16) then attention output o (fp32)
__device__ float g_k[TOTAL];        // K(bf16) then MLP hidden (fp32)
__device__ float g_v[TOTAL];        // V fp32
__device__ float g_attn[BB*16*4*256];
__device__ float g_mean[BB*SS*CC];
__device__ float g_rsig[BB*SS*CC];

// ---------------- helpers ----------------
__device__ __forceinline__ float gelu_tanh(float x) {
    float x3 = x * x * x;
    return 0.5f * x * (1.0f + tanhf(0.7978845608028654f * (x + 0.044715f * x3)));
}
__device__ __forceinline__ unsigned packbf(float lo, float hi) {
    __nv_bfloat162 h = __floats2bfloat162_rn(lo, hi);   // .x = lo (low half)
    return *(unsigned*)&h;
}
__device__ __forceinline__ int tok_of(int n, int slot) {
    int nr = n >> 2, nc = n & 3;
    int pr = nr * 4 + (slot >> 2), pc = nc * 4 + (slot & 3);
    return (((pr + 2) & 15) << 4) | ((pc + 2) & 15);
}
__device__ __forceinline__ int region_of(int p) { return p < 12 ? 0 : (p < 14 ? 1 : 2); }

// ---------------- stats: per-(b,s,c) mean & rsqrt(var+eps) over 256 spatial ----------------
__global__ __launch_bounds__(256) void stats_kernel(const float* __restrict__ in,
                                                    float* __restrict__ mean,
                                                    float* __restrict__ rsig) {
    int row  = blockIdx.x * 8 + (threadIdx.x >> 5);
    int lane = threadIdx.x & 31;
    const float* p = in + (size_t)row * 256 + lane * 8;
    float4 a = *(const float4*)p;
    float4 b = *(const float4*)(p + 4);
    float s = a.x + a.y + a.z + a.w + b.x + b.y + b.z + b.w;
    float q = a.x*a.x + a.y*a.y + a.z*a.z + a.w*a.w
            + b.x*b.x + b.y*b.y + b.z*b.z + b.w*b.w;
#pragma unroll
    for (int off = 16; off; off >>= 1) {
        s += __shfl_xor_sync(0xffffffffu, s, off);
        q += __shfl_xor_sync(0xffffffffu, q, off);
    }
    if (lane == 0) {
        float m = s * (1.0f / 256.0f);
        float var = q * (1.0f / 256.0f) - m * m;
        mean[row] = m;
        rsig[row] = rsqrtf(var + 1e-5f);
    }
}

// ---------------- bf16 tensor-core pointwise GEMM ----------------
// Per bs token: Out[d=128][hw=256] = sum_c Xn[c][hw] * W[c][d] + bias
// Block = (mat, bs). 8 warps (2x4), warp tile 64x64, mma m16n8k16 bf16.
// Smem holds channel-PAIRS packed in uint32 (low = even c) matching the
// bf16 fragment layout, so every LDS feeds K=2.
// mode: 0 store, 1 gelu, 2 +residual.  bf16_mask: per-mat bf16 output.
// smean/srsig non-null (mode2): fused InstanceNorm stats of the output.
__global__ __launch_bounds__(256, 1) void pw_bf16_kernel(
    const float* __restrict__ X,
    const float* __restrict__ W0, const float* __restrict__ W1, const float* __restrict__ W2,
    const float* __restrict__ B0, const float* __restrict__ B1, const float* __restrict__ B2,
    float* __restrict__ O0, float* __restrict__ O1, float* __restrict__ O2,
    const float* __restrict__ mean, const float* __restrict__ rsig,
    const float* __restrict__ res, int mode, int bf16_mask,
    float* __restrict__ smean, float* __restrict__ srsig)
{
    __shared__ unsigned Xp[16][264];   // [c/2][hw] packed pairs; 264%32==8 -> conflict-free
    __shared__ unsigned Wp[16][136];   // [c/2][d]
    __shared__ float Ssum[128][4];
    __shared__ float Ssq[128][4];

    const int bs  = blockIdx.y;
    const int mat = blockIdx.x;
    const float* W  = (mat == 0) ? W0 : (mat == 1 ? W1 : W2);
    const float* Bp = (mat == 0) ? B0 : (mat == 1 ? B1 : B2);
    float*       O  = (mat == 0) ? O0 : (mat == 1 ? O1 : O2);
    const float* Xb = X + (size_t)bs * TOK_STRIDE;

    const int tid  = threadIdx.x;
    const int warp = tid >> 5, lane = tid & 31;
    const int gid  = lane >> 2, tig = lane & 3;
    const int m_warp = (warp >> 2) * 64;
    const int n_warp = (warp & 3) * 64;

    float acc[4][8][4];
#pragma unroll
    for (int a = 0; a < 4; a++)
#pragma unroll
        for (int b = 0; b < 8; b++)
#pragma unroll
            for (int c = 0; c < 4; c++) acc[a][b][c] = 0.0f;

    unsigned xu[4][4], wu[2][4];

#define LOAD_TILE(K0) do {                                                         \
    _Pragma("unroll")                                                              \
    for (int it = 0; it < 4; it++) {                                               \
        int task = tid + it * 256;                                                 \
        int kp = task >> 6, hw = (task & 63) << 2;                                 \
        int c0 = (K0) + kp * 2;                                                    \
        float4 xa = *(const float4*)&Xb[(size_t)c0 * 256 + hw];                    \
        float4 xc = *(const float4*)&Xb[(size_t)(c0 + 1) * 256 + hw];              \
        if (mean) {                                                                \
            float m0 = __ldg(&mean[bs * 128 + c0]);                                \
            float r0 = __ldg(&rsig[bs * 128 + c0]);                                \
            float m1 = __ldg(&mean[bs * 128 + c0 + 1]);                            \
            float r1 = __ldg(&rsig[bs * 128 + c0 + 1]);                            \
            xa.x = (xa.x - m0) * r0; xa.y = (xa.y - m0) * r0;                      \
            xa.z = (xa.z - m0) * r0; xa.w = (xa.w - m0) * r0;                      \
            xc.x = (xc.x - m1) * r1; xc.y = (xc.y - m1) * r1;                      \
            xc.z = (xc.z - m1) * r1; xc.w = (xc.w - m1) * r1;                      \
        }                                                                          \
        xu[it][0] = packbf(xa.x, xc.x); xu[it][1] = packbf(xa.y, xc.y);            \
        xu[it][2] = packbf(xa.z, xc.z); xu[it][3] = packbf(xa.w, xc.w);            \
    }                                                                              \
    _Pragma("unroll")                                                              \
    for (int it = 0; it < 2; it++) {                                               \
        int task = tid + it * 256;                                                 \
        int kp = task >> 5, m4 = (task & 31) << 2;                                 \
        int c0 = (K0) + kp * 2;                                                    \
        float4 wa = *(const float4*)&W[c0 * 128 + m4];                             \
        float4 wc = *(const float4*)&W[(c0 + 1) * 128 + m4];                       \
        wu[it][0] = packbf(wa.x, wc.x); wu[it][1] = packbf(wa.y, wc.y);            \
        wu[it][2] = packbf(wa.z, wc.z); wu[it][3] = packbf(wa.w, wc.w);            \
    }                                                                              \
} while (0)

#define STORE_TILE() do {                                                          \
    _Pragma("unroll")                                                              \
    for (int it = 0; it < 4; it++) {                                               \
        int task = tid + it * 256;                                                 \
        int kp = task >> 6, hw = (task & 63) << 2;                                 \
        *(uint4*)&Xp[kp][hw] = make_uint4(xu[it][0], xu[it][1], xu[it][2], xu[it][3]); \
    }                                                                              \
    _Pragma("unroll")                                                              \
    for (int it = 0; it < 2; it++) {                                               \
        int task = tid + it * 256;                                                 \
        int kp = task >> 5, m4 = (task & 31) << 2;                                 \
        *(uint4*)&Wp[kp][m4] = make_uint4(wu[it][0], wu[it][1], wu[it][2], wu[it][3]); \
    }                                                                              \
} while (0)

    LOAD_TILE(0);
#pragma unroll 1
    for (int t = 0; t < 4; t++) {
        __syncthreads();
        STORE_TILE();
        __syncthreads();
        if (t < 3) LOAD_TILE((t + 1) * 32);

#pragma unroll
        for (int g = 0; g < 2; g++) {
            const int kb = g * 8;
            unsigned af[4][4];
#pragma unroll
            for (int mt = 0; mt < 4; mt++) {
                int mb = m_warp + mt * 16;
                af[mt][0] = Wp[kb + tig    ][mb + gid    ];
                af[mt][1] = Wp[kb + tig    ][mb + gid + 8];
                af[mt][2] = Wp[kb + tig + 4][mb + gid    ];
                af[mt][3] = Wp[kb + tig + 4][mb + gid + 8];
            }
#pragma unroll
            for (int nt = 0; nt < 8; nt++) {
                int nb = n_warp + nt * 8 + gid;
                unsigned b0 = Xp[kb + tig    ][nb];
                unsigned b1 = Xp[kb + tig + 4][nb];
#pragma unroll
                for (int mt = 0; mt < 4; mt++) {
                    float* c = acc[mt][nt];
                    asm volatile(
                        "mma.sync.aligned.m16n8k16.row.col.f32.bf16.bf16.f32 "
                        "{%0,%1,%2,%3}, {%4,%5,%6,%7}, {%8,%9}, {%0,%1,%2,%3};"
                        : "+f"(c[0]), "+f"(c[1]), "+f"(c[2]), "+f"(c[3])
                        : "r"(af[mt][0]), "r"(af[mt][1]), "r"(af[mt][2]), "r"(af[mt][3]),
                          "r"(b0), "r"(b1));
                }
            }
        }
    }
#undef LOAD_TILE
#undef STORE_TILE

    // ---------- epilogue ----------
    const float* Rb = res ? res + (size_t)bs * TOK_STRIDE : nullptr;
    float*       Of = O + (size_t)bs * TOK_STRIDE;
    __nv_bfloat16* Oh = (__nv_bfloat16*)O + (size_t)bs * TOK_STRIDE;
    const bool obf = (bf16_mask >> mat) & 1;
    const bool do_stats = (smean != nullptr);

    float ssum[4][2], ssq[4][2];
#pragma unroll
    for (int mt = 0; mt < 4; mt++) { ssum[mt][0]=ssum[mt][1]=0.f; ssq[mt][0]=ssq[mt][1]=0.f; }

#pragma unroll
    for (int mt = 0; mt < 4; mt++) {
        int m0 = m_warp + mt * 16 + gid;
        float bv0 = __ldg(&Bp[m0]);
        float bv1 = __ldg(&Bp[m0 + 8]);
#pragma unroll
        for (int nt = 0; nt < 8; nt++) {
            int col = n_warp + nt * 8 + 2 * tig;
            float2 o0 = make_float2(acc[mt][nt][0] + bv0, acc[mt][nt][1] + bv0);
            float2 o1 = make_float2(acc[mt][nt][2] + bv1, acc[mt][nt][3] + bv1);
            if (mode == 1) {
                o0.x = gelu_tanh(o0.x); o0.y = gelu_tanh(o0.y);
                o1.x = gelu_tanh(o1.x); o1.y = gelu_tanh(o1.y);
            } else if (mode == 2) {
                float2 r0 = *(const float2*)&Rb[m0 * 256 + col];
                float2 r1 = *(const float2*)&Rb[(m0 + 8) * 256 + col];
                o0.x += r0.x; o0.y += r0.y;
                o1.x += r1.x; o1.y += r1.y;
            }
            if (do_stats) {
                ssum[mt][0] += o0.x + o0.y;  ssq[mt][0] += o0.x*o0.x + o0.y*o0.y;
                ssum[mt][1] += o1.x + o1.y;  ssq[mt][1] += o1.x*o1.x + o1.y*o1.y;
            }
            if (obf) {
                __nv_bfloat162 h0 = __floats2bfloat162_rn(o0.x, o0.y);
                __nv_bfloat162 h1 = __floats2bfloat162_rn(o1.x, o1.y);
                *(__nv_bfloat162*)&Oh[m0 * 256 + col]       = h0;
                *(__nv_bfloat162*)&Oh[(m0 + 8) * 256 + col] = h1;
            } else {
                *(float2*)&Of[m0 * 256 + col]       = o0;
                *(float2*)&Of[(m0 + 8) * 256 + col] = o1;
            }
        }
    }

    if (do_stats) {
#pragma unroll
        for (int mt = 0; mt < 4; mt++)
#pragma unroll
            for (int ab = 0; ab < 2; ab++) {
                float s = ssum[mt][ab], q2 = ssq[mt][ab];
                s  += __shfl_xor_sync(0xffffffffu, s, 1);
                s  += __shfl_xor_sync(0xffffffffu, s, 2);
                q2 += __shfl_xor_sync(0xffffffffu, q2, 1);
                q2 += __shfl_xor_sync(0xffffffffu, q2, 2);
                if (tig == 0) {
                    int row = m_warp + mt * 16 + ab * 8 + gid;
                    Ssum[row][warp & 3] = s;
                    Ssq[row][warp & 3]  = q2;
                }
            }
        __syncthreads();
        if (tid < 128) {
            float s  = Ssum[tid][0] + Ssum[tid][1] + Ssum[tid][2] + Ssum[tid][3];
            float q2 = Ssq[tid][0]  + Ssq[tid][1]  + Ssq[tid][2]  + Ssq[tid][3];
            float m  = s * (1.0f / 256.0f);
            float var = q2 * (1.0f / 256.0f) - m * m;
            smean[bs * 128 + tid] = m;
            srsig[bs * 128 + tid] = rsqrtf(var + 1e-5f);
        }
    }
}

// ---------------- scores + mask + softmax (bf16 Q,K inputs) ----------------
__global__ __launch_bounds__(256) void scores_kernel(const __nv_bfloat16* __restrict__ qb,
                                                     const __nv_bfloat16* __restrict__ kb,
                                                     float* __restrict__ attn) {
    __shared__ float qs[16][260];
    __shared__ float ks[16][260];
    __shared__ int toks[16];
    const int blk = blockIdx.x;
    const int h = blk & 3;
    const int bn = blk >> 2;
    const int n = bn & 15;
    const int b = bn >> 4;
    const int tid = threadIdx.x;
    if (tid < 16) toks[tid] = tok_of(n, tid);
    __syncthreads();

    const int t = tid >> 4, s = tid & 15;
    float ax = 0.f, ay = 0.f, az = 0.f, aw = 0.f;

    for (int ch = 0; ch < 32; ch++) {
        __syncthreads();
#pragma unroll
        for (int j = 0; j < 4; j++) {
            int p = tid + j * 256;          // 0..1023
            int row = p >> 5;               // 0..31
            int c8 = (p & 31) << 3;         // bf16 elem offset, 8 at a time
            const __nv_bfloat16* src = (row < 16) ? qb : kb;
            int tok = toks[row & 15];
            const __nv_bfloat16* g = src + ((size_t)(b * 256 + tok)) * TOK_STRIDE
                                         + h * 8192 + ch * 256 + c8;
            uint4 u = *(const uint4*)g;
            float2 f0 = __bfloat1622float2(*(__nv_bfloat162*)&u.x);
            float2 f1 = __bfloat1622float2(*(__nv_bfloat162*)&u.y);
            float2 f2 = __bfloat1622float2(*(__nv_bfloat162*)&u.z);
            float2 f3 = __bfloat1622float2(*(__nv_bfloat162*)&u.w);
            float* dst = (row < 16 ? qs : ks)[row & 15] + c8;
            *(float4*)dst       = make_float4(f0.x, f0.y, f1.x, f1.y);
            *(float4*)(dst + 4) = make_float4(f2.x, f2.y, f3.x, f3.y);
        }
        __syncthreads();
#pragma unroll
        for (int i4 = 0; i4 < 64; i4++) {
            float4 qv = *(float4*)&qs[t][i4 * 4];
            float4 kv = *(float4*)&ks[s][i4 * 4];
            ax += qv.x * kv.x; ay += qv.y * kv.y;
            az += qv.z * kv.z; aw += qv.w * kv.w;
        }
    }
    float acc = (ax + ay) + (az + aw);
    acc *= 6.9053396600248786e-4f;

    {
        int nr = n >> 2, nc = n & 3;
        int idt = region_of(nr * 4 + (t >> 2)) * 3 + region_of(nc * 4 + (t & 3));
        int ids = region_of(nr * 4 + (s >> 2)) * 3 + region_of(nc * 4 + (s & 3));
        if (idt != ids) acc -= 1e9f;
    }

    float m = acc;
#pragma unroll
    for (int off = 8; off; off >>= 1)
        m = fmaxf(m, __shfl_xor_sync(0xffffffffu, m, off, 16));
    float e = expf(acc - m);
    float sum = e;
#pragma unroll
    for (int off = 8; off; off >>= 1)
        sum += __shfl_xor_sync(0xffffffffu, sum, off, 16);

    attn[blk * 256 + tid] = e / sum;
}

// ---------------- attn @ V ----------------
__global__ __launch_bounds__(256, 2) void apply_attn_kernel(const float* __restrict__ attn,
                                                            const float* __restrict__ val,
                                                            float* __restrict__ out) {
    __shared__ float at_s[16][16];
    __shared__ int toks[16];
    const int bn = blockIdx.y;
    const int b = bn >> 4, n = bn & 15;
    const int tid = threadIdx.x;
    if (tid < 16) toks[tid] = tok_of(n, tid);

    const int f0 = blockIdx.x * 1024 + tid * 4;
    const int c = f0 >> 8;
    const int hw = f0 & 255;
    const int head = c >> 5;
    at_s[tid >> 4][tid & 15] = attn[(bn * 4 + head) * 256 + tid];
    __syncthreads();

    float4 v4[16];
#pragma unroll
    for (int s = 0; s < 16; s++)
        v4[s] = *(const float4*)&val[((size_t)(b * 256 + toks[s])) * TOK_STRIDE + c * 256 + hw];

#pragma unroll
    for (int t = 0; t < 16; t++) {
        float4 o = make_float4(0.f, 0.f, 0.f, 0.f);
#pragma unroll
        for (int s = 0; s < 16; s++) {
            float a = at_s[t][s];
            o.x += a * v4[s].x; o.y += a * v4[s].y;
            o.z += a * v4[s].z; o.w += a * v4[s].w;
        }
        *(float4*)&out[((size_t)(b * 256 + toks[t])) * TOK_STRIDE + c * 256 + hw] = o;
    }
}

// ---------------- launch ----------------
extern "C" void kernel_launch(void* const* d_in, const int* in_sizes, int n_in,
                              void* d_out, int out_size) {
    const float* v  = (const float*)d_in[0];
    const float* wq = (const float*)d_in[1];
    const float* bq = (const float*)d_in[2];
    const float* wk = (const float*)d_in[3];
    const float* bk = (const float*)d_in[4];
    const float* wv = (const float*)d_in[5];
    const float* bv = (const float*)d_in[6];
    const float* wo = (const float*)d_in[7];
    const float* bo = (const float*)d_in[8];
    const float* w1 = (const float*)d_in[9];
    const float* b1 = (const float*)d_in[10];
    const float* w2 = (const float*)d_in[11];
    const float* b2 = (const float*)d_in[12];
    float* out = (float*)d_out;

    float *q, *k, *vvp, *attn, *mean, *rsig;
    cudaGetSymbolAddress((void**)&q,    g_q);
    cudaGetSymbolAddress((void**)&k,    g_k);
    cudaGetSymbolAddress((void**)&vvp,  g_v);
    cudaGetSymbolAddress((void**)&attn, g_attn);
    cudaGetSymbolAddress((void**)&mean, g_mean);
    cudaGetSymbolAddress((void**)&rsig, g_rsig);

    // 1. InstanceNorm stats of v
    stats_kernel<<<32768, 256>>>(v, mean, rsig);
    // 2. Q,K,V projections; Q,K stored bf16, V fp32; norm fused
    pw_bf16_kernel<<<dim3(3, 2048), 256>>>(v, wq, wk, wv, bq, bk, bv,
                                           q, k, vvp, mean, rsig, nullptr,
                                           0, 0b011, nullptr, nullptr);
    // 3. scores + mask + softmax (bf16 Q,K)
    scores_kernel<<<512, 256>>>((const __nv_bfloat16*)q, (const __nv_bfloat16*)k, attn);
    // 4. o = attn @ V (fp32, overwrites Q buffer)
    apply_attn_kernel<<<dim3(32, 128), 256>>>(attn, vvp, q);
    // 5. mid = v + pw(o, w_o); InstanceNorm stats of mid fused into epilogue
    pw_bf16_kernel<<<dim3(1, 2048), 256>>>(q, wo, wo, wo, bo, bo, bo,
                                           out, out, out, nullptr, nullptr, v,
                                           2, 0, mean, rsig);
    // 6. h = gelu(pw(norm(mid), w1))  (overwrites K buffer, fp32)
    pw_bf16_kernel<<<dim3(1, 2048), 256>>>(out, w1, w1, w1, b1, b1, b1,
                                           k, k, k, mean, rsig, nullptr,
                                           1, 0, nullptr, nullptr);
    // 7. out = mid + pw(h, w2)
    pw_bf16_kernel<<<dim3(1, 2048), 256>>>(k, w2, w2, w2, b2, b2, b2,
                                           out, out, out, nullptr, nullptr, out,
                                           2, 0, nullptr, nullptr);
}